// round 12
// baseline (speedup 1.0000x reference)
#include <cuda_runtime.h>

#define Bb   8
#define HW   1024
#define Cc   512
#define C4   128
#define NBLK 128
#define NTHR 512
// dynamic smem: x-tile 128 KB + scratch 32 KB (colsum staging / warp-acc / psum)
#define DYN_BYTES (128 * 1024 + 32 * 1024)

// ---------------- sync counters, one per 128-B line ---------------------------
struct alignas(128) Line { unsigned v; unsigned pad[31]; };
__device__ Line c_cs[8];    // colsum tickets per batch (16 each; 16th = winner)
__device__ Line c_ks;       // Ksum published (8 winners)
__device__ Line c_u;        // u published (8 winners)
__device__ Line c_ep[8];    // epilogue tickets per batch (16 each)
__device__ Line c_fin;      // 8 epilogue winners; 8th resets shared counters
__device__ unsigned g_mnk[Bb] = {0xFFFFFFFFu,0xFFFFFFFFu,0xFFFFFFFFu,0xFFFFFFFFu,
                                 0xFFFFFFFFu,0xFFFFFFFFu,0xFFFFFFFFu,0xFFFFFFFFu};
__device__ unsigned g_mxk[Bb] = {0,0,0,0,0,0,0,0};

// ---------------- data scratch (fully rewritten every launch) -----------------
__device__ __align__(16) float4 g_partial4[Bb][16][C4];
__device__ __align__(16) float  g_ksum[Bb][Cc];
__device__ __align__(16) float  g_u[Bb][Cc];
__device__ float g_dot[Bb][HW];

__device__ __forceinline__ unsigned enc(float f) {
    unsigned u = __float_as_uint(f);
    return (u & 0x80000000u) ? ~u : (u | 0x80000000u);
}
__device__ __forceinline__ float dec(unsigned k) {
    return (k & 0x80000000u) ? __uint_as_float(k ^ 0x80000000u)
                             : __uint_as_float(~k);
}

#define WAITGE(lineptr, tgt)                                          \
    do { if (t == 0) {                                                \
             while (*(volatile const unsigned*)&(lineptr)->v          \
                    < (unsigned)(tgt)) {}                             \
             __threadfence();                                         \
         }                                                            \
         __syncthreads();                                             \
    } while (0)

__global__ void __launch_bounds__(NTHR)
fused_kernel(const float* __restrict__ x,
             const float* __restrict__ conv_w, const float* __restrict__ conv_b,
             const float* __restrict__ q_w,
             const float* __restrict__ k_w,    const float* __restrict__ k_b,
             float* __restrict__ out)
{
    extern __shared__ float dynsh[];
    float4* tile4   = reinterpret_cast<float4*>(dynsh);        // 8192 float4, 128 KB
    float*  scratch = dynsh + 32768;                           // 8192 floats, 32 KB
    __shared__ __align__(16) float sXsum[Cc];
    __shared__ __align__(16) float sXr[Cc];
    __shared__ __align__(16) float sKs[Cc];
    __shared__ __align__(16) float sV[Cc];
    __shared__ __align__(16) float sW[Cc];
    __shared__ __align__(16) float sU[Cc];
    __shared__ float sdot[64];
    __shared__ unsigned sh_tk;

    const int g    = blockIdx.x;
    const int t    = threadIdx.x;
    const int warp = t >> 5, lane = t & 31;
    const int b_own = g >> 4, s_own = g & 15;
    const int c4t = t & 127, rs = t >> 7;

    // ============ P1: x tile -> smem (+colsum partial) =======================
    {
        const float4* base = reinterpret_cast<const float4*>(x)
                           + ((size_t)(b_own * HW + s_own * 64 + rs * 16)) * C4 + c4t;
        float4 acc = make_float4(0.f, 0.f, 0.f, 0.f);
#pragma unroll
        for (int p = 0; p < 16; ++p) {
            float4 v = base[(size_t)p * C4];
            tile4[(rs * 16 + p) * C4 + c4t] = v;
            acc.x += v.x; acc.y += v.y; acc.z += v.z; acc.w += v.w;
        }
        float4* shP = reinterpret_cast<float4*>(scratch);      // [4][128] staging
        shP[rs * C4 + c4t] = acc;
        __syncthreads();
        if (t < C4) {
            float4 a = shP[t], p1 = shP[C4 + t], p2 = shP[2 * C4 + t], p3 = shP[3 * C4 + t];
            a.x += p1.x + p2.x + p3.x;  a.y += p1.y + p2.y + p3.y;
            a.z += p1.z + p2.z + p3.z;  a.w += p1.w + p2.w + p3.w;
            g_partial4[b_own][s_own][t] = a;
        }
    }
    // colsum ticket: 16th arriver of each batch becomes that batch's mid-block
    __syncthreads();
    if (t == 0) { __threadfence(); sh_tk = atomicAdd(&c_cs[b_own].v, 1u); }
    __syncthreads();

    if (sh_tk == 15u) {
        // ================= WINNER: entire mid-chain for batch b_own ==========
        __threadfence();                     // see other blocks' partials
        const int b = b_own;
        // ---- Xsum (fixed-order reduce)
        {
            const float* gp = &g_partial4[0][0][0].x;
            float a = 0.f;
#pragma unroll
            for (int sp = 0; sp < 16; ++sp)
                a += gp[(b * 16 + sp) * Cc + t];
            sXsum[t] = a;
        }
        __syncthreads();
        // ---- xr = (conv_w + I) Xsum + HW*conv_b   (warp-per-row, 32 rows/warp)
        {
            const float4* W4 = reinterpret_cast<const float4*>(conv_w);
            const float4* X4 = reinterpret_cast<const float4*>(sXsum);
#pragma unroll 4
            for (int r = 0; r < 32; ++r) {
                const int o = warp * 32 + r;
                float acc = 0.f;
#pragma unroll
                for (int k = 0; k < 4; ++k) {
                    const float4 wv = W4[(size_t)o * C4 + lane + 32 * k];
                    const float4 xv = X4[lane + 32 * k];
                    acc += wv.x * xv.x + wv.y * xv.y + wv.z * xv.z + wv.w * xv.w;
                }
#pragma unroll
                for (int off = 16; off; off >>= 1)
                    acc += __shfl_xor_sync(0xffffffffu, acc, off);
                if (lane == 0)
                    sXr[o] = acc + (float)HW * conv_b[o] + sXsum[o];
            }
        }
        __syncthreads();
        // ---- Ksum = k_w xr + HW*k_b
        {
            const float4* W4 = reinterpret_cast<const float4*>(k_w);
            const float4* X4 = reinterpret_cast<const float4*>(sXr);
#pragma unroll 4
            for (int r = 0; r < 32; ++r) {
                const int o = warp * 32 + r;
                float acc = 0.f;
#pragma unroll
                for (int k = 0; k < 4; ++k) {
                    const float4 wv = W4[(size_t)o * C4 + lane + 32 * k];
                    const float4 xv = X4[lane + 32 * k];
                    acc += wv.x * xv.x + wv.y * xv.y + wv.z * xv.z + wv.w * xv.w;
                }
#pragma unroll
                for (int off = 16; off; off >>= 1)
                    acc += __shfl_xor_sync(0xffffffffu, acc, off);
                if (lane == 0)
                    sKs[o] = acc + (float)HW * k_b[o];
            }
        }
        __syncthreads();
        g_ksum[b][t] = sKs[t];               // publish (coalesced)
        __threadfence(); __syncthreads();
        if (t == 0) atomicAdd(&c_ks.v, 1u);

        // ---- wait #1: all 8 Ksums
        WAITGE(&c_ks, 8);
        {
            float tot = 0.f;
#pragma unroll
            for (int bb = 0; bb < Bb; ++bb) tot += g_ksum[bb][t];
            sV[t] = tot - sKs[t];
        }
        __syncthreads();
        // ---- w = q_w^T v   (transposed: warp-accumulators in scratch, reduce)
        {
            const float4* W4 = reinterpret_cast<const float4*>(q_w);
            float4 acc4[4];
#pragma unroll
            for (int k = 0; k < 4; ++k) acc4[k] = make_float4(0.f, 0.f, 0.f, 0.f);
#pragma unroll 4
            for (int r = 0; r < 32; ++r) {
                const int o = warp * 32 + r;
                const float vo = sV[o];
#pragma unroll
                for (int k = 0; k < 4; ++k) {
                    const float4 wv = W4[(size_t)o * C4 + lane + 32 * k];
                    acc4[k].x += wv.x * vo; acc4[k].y += wv.y * vo;
                    acc4[k].z += wv.z * vo; acc4[k].w += wv.w * vo;
                }
            }
            float4* sAcc4 = reinterpret_cast<float4*>(scratch);   // [16][128] f4
#pragma unroll
            for (int k = 0; k < 4; ++k)
                sAcc4[warp * C4 + lane + 32 * k] = acc4[k];
        }
        __syncthreads();
        {
            float s = 0.f;
#pragma unroll
            for (int ww = 0; ww < 16; ++ww) s += scratch[ww * Cc + t];
            sW[t] = s;
        }
        __syncthreads();
        // ---- u = conv_w^T w + w
        {
            const float4* W4 = reinterpret_cast<const float4*>(conv_w);
            float4 acc4[4];
#pragma unroll
            for (int k = 0; k < 4; ++k) acc4[k] = make_float4(0.f, 0.f, 0.f, 0.f);
#pragma unroll 4
            for (int r = 0; r < 32; ++r) {
                const int o = warp * 32 + r;
                const float vo = sW[o];
#pragma unroll
                for (int k = 0; k < 4; ++k) {
                    const float4 wv = W4[(size_t)o * C4 + lane + 32 * k];
                    acc4[k].x += wv.x * vo; acc4[k].y += wv.y * vo;
                    acc4[k].z += wv.z * vo; acc4[k].w += wv.w * vo;
                }
            }
            float4* sAcc4 = reinterpret_cast<float4*>(scratch);
#pragma unroll
            for (int k = 0; k < 4; ++k)
                sAcc4[warp * C4 + lane + 32 * k] = acc4[k];
        }
        __syncthreads();
        {
            float s = sW[t];                 // +w residual
#pragma unroll
            for (int ww = 0; ww < 16; ++ww) s += scratch[ww * Cc + t];
            g_u[b][t] = s;                   // publish (coalesced)
        }
        __threadfence(); __syncthreads();
        if (t == 0) atomicAdd(&c_u.v, 1u);
    }

    // ============ wait #2: all 8 u vectors ===================================
    WAITGE(&c_u, 8);

    // ============ dot from smem tile + minmax + epilogue =====================
    {
        sU[t] = g_u[b_own][t];               // 2 KB only
        __syncthreads();

        float* psum = scratch;               // [64][128] (winner done with sAcc)
        const float4 uv = reinterpret_cast<const float4*>(sU)[c4t];
#pragma unroll
        for (int p = 0; p < 16; ++p) {
            const float4 xv = tile4[(rs * 16 + p) * C4 + c4t];
            psum[(rs * 16 + p) * C4 + c4t] =
                xv.x * uv.x + xv.y * uv.y + xv.z * uv.z + xv.w * uv.w;
        }
        __syncthreads();
#pragma unroll
        for (int rr = 0; rr < 4; ++rr) {
            const int row = warp * 4 + rr;
            float sm = psum[row * C4 + lane] + psum[row * C4 + lane + 32]
                     + psum[row * C4 + lane + 64] + psum[row * C4 + lane + 96];
#pragma unroll
            for (int off = 16; off; off >>= 1)
                sm += __shfl_xor_sync(0xffffffffu, sm, off);
            if (lane == 0) { sdot[row] = sm; g_dot[b_own][s_own * 64 + row] = sm; }
        }
    }
    __syncthreads();
    if (warp == 0) {
        float v0 = sdot[lane], v1 = sdot[lane + 32];
        float mn = fminf(v0, v1), mx = fmaxf(v0, v1);
#pragma unroll
        for (int off = 16; off; off >>= 1) {
            mn = fminf(mn, __shfl_xor_sync(0xffffffffu, mn, off));
            mx = fmaxf(mx, __shfl_xor_sync(0xffffffffu, mx, off));
        }
        if (lane == 0) {
            atomicMin(&g_mnk[b_own], enc(mn));
            atomicMax(&g_mxk[b_own], enc(mx));
        }
    }
    // epilogue ticket: 16th arriver of each batch writes outputs + resets
    __syncthreads();
    if (t == 0) { __threadfence(); sh_tk = atomicAdd(&c_ep[b_own].v, 1u); }
    __syncthreads();
    if (sh_tk == 15u) {
        __threadfence();
        const float mn = dec(g_mnk[b_own]);
        const float mx = dec(g_mxk[b_own]);
        const float inv = 1.0f / (mx - mn);
#pragma unroll
        for (int i = 0; i < 2; ++i) {
            const int idx = t + i * NTHR;
            const float z = ((g_dot[b_own][idx] - mn) * inv - 0.65f) / 0.15f;
            out[b_own * HW + idx] = 1.0f / (1.0f + __expf(-z));
        }
        __syncthreads();
        if (t == 0) {
            g_mnk[b_own] = 0xFFFFFFFFu;      // reset per-batch state
            g_mxk[b_own] = 0u;
            c_cs[b_own].v = 0u;
            c_ep[b_own].v = 0u;
            __threadfence();
            unsigned old = atomicAdd(&c_fin.v, 1u);
            if (old == 7u) {                 // 8th winner: reset shared counters
                c_ks.v = 0u; c_u.v = 0u; c_fin.v = 0u;
                __threadfence();
            }
        }
    }
}

// ---------------------------------------------------------------------------
extern "C" void kernel_launch(void* const* d_in, const int* in_sizes, int n_in,
                              void* d_out, int out_size) {
    const float* x      = (const float*)d_in[0];
    const float* conv_w = (const float*)d_in[1];
    const float* conv_b = (const float*)d_in[2];
    const float* q_w    = (const float*)d_in[3];
    // d_in[4] = q_b: per-batch constant, cancels in min/max normalization.
    const float* k_w    = (const float*)d_in[5];
    const float* k_b    = (const float*)d_in[6];
    float* out = (float*)d_out;

    cudaFuncSetAttribute(fused_kernel,
                         cudaFuncAttributeMaxDynamicSharedMemorySize,
                         DYN_BYTES);
    fused_kernel<<<NBLK, NTHR, DYN_BYTES>>>(x, conv_w, conv_b, q_w, k_w, k_b, out);
}

// round 13
// speedup vs baseline: 2.0925x; 2.0925x over previous
#include <cuda_runtime.h>

#define Bb   8
#define HW   1024
#define Cc   512
#define C4   128
#define NBLK 128
#define NTHR 512
#define DYN_BYTES (64 * 1024)   // wbuf 64KB

// ---------------- sync counters, one per 128-B line ---------------------------
struct alignas(128) Line { unsigned v; unsigned pad[31]; };
__device__ Line c_cs[8];    // colsum tickets per batch (16 each)
__device__ Line c_xs;       // xsum winners (8)
__device__ Line c_xr[4];    // xr arrivals (64, 16/line)
__device__ Line c_ks[4];    // ksum arrivals (64, 16/line)
__device__ Line c_wp;       // wpart arrivals (16)
__device__ Line c_up;       // upart arrivals (16)
__device__ Line c_ep[8];    // epilogue arrivals per batch (16 each)
__device__ Line c_fin;      // 128 arrivals; 128th resets everything (never polled)
__device__ unsigned g_mnk[Bb] = {0xFFFFFFFFu,0xFFFFFFFFu,0xFFFFFFFFu,0xFFFFFFFFu,
                                 0xFFFFFFFFu,0xFFFFFFFFu,0xFFFFFFFFu,0xFFFFFFFFu};
__device__ unsigned g_mxk[Bb] = {0,0,0,0,0,0,0,0};

// ---------------- data scratch (fully rewritten every launch) -----------------
__device__ __align__(16) float4 g_partial4[Bb][16][C4];
__device__ __align__(16) float  g_xsum[Bb][Cc];
__device__ __align__(16) float  g_xr[Bb][Cc];
__device__ __align__(16) float  g_ksum[Bb][Cc];
__device__ __align__(16) float  g_wpart[16][Bb][Cc];
__device__ __align__(16) float  g_w[Bb][Cc];
__device__ __align__(16) float  g_upart[16][Bb][Cc];

__device__ __forceinline__ unsigned enc(float f) {
    unsigned u = __float_as_uint(f);
    return (u & 0x80000000u) ? ~u : (u | 0x80000000u);
}
__device__ __forceinline__ float dec(unsigned k) {
    return (k & 0x80000000u) ? __uint_as_float(k ^ 0x80000000u)
                             : __uint_as_float(~k);
}

#define ARRIVE(lineptr)                                               \
    do { __syncthreads();                                             \
         if (t == 0) { __threadfence(); atomicAdd(&(lineptr)->v, 1u); } \
    } while (0)
#define WAITGE(arr, n, tgt)                                           \
    do { if (t == 0) {                                                \
             unsigned s_;                                             \
             do { s_ = 0;                                             \
                  _Pragma("unroll")                                   \
                  for (int i_ = 0; i_ < (n); ++i_)                    \
                      s_ += *(volatile const unsigned*)&(arr)[i_].v;  \
             } while (s_ < (unsigned)(tgt));                          \
             __threadfence();                                         \
         }                                                            \
         __syncthreads();                                             \
    } while (0)

__global__ void __launch_bounds__(NTHR)
fused_kernel(const float* __restrict__ x,
             const float* __restrict__ conv_w, const float* __restrict__ conv_b,
             const float* __restrict__ q_w,
             const float* __restrict__ k_w,    const float* __restrict__ k_b,
             float* __restrict__ out)
{
    extern __shared__ float dynsh[];
    float*  wbuf  = dynsh;                                  // 16384 f (64 KB)
    float4* wbuf4 = reinterpret_cast<float4*>(dynsh);
    __shared__ __align__(16) float shA[Bb][Cc];             // 16 KB
    __shared__ __align__(16) float shB[Cc];                 // 2 KB
    __shared__ __align__(16) float psum[64][C4];            // 32 KB
    __shared__ float s_part[16][Bb];
    __shared__ float shW[Bb][32];
    __shared__ float sdot[64];
    __shared__ unsigned sh_tk;
    float4* shA4 = reinterpret_cast<float4*>(shA);

    const int g    = blockIdx.x;
    const int t    = threadIdx.x;
    const int warp = t >> 5, lane = t & 31;
    const int b_own = g >> 4, s_own = g & 15;
    const int c4t = t & 127, rs = t >> 7;

    // ============ P1: x tile -> registers (+colsum) & weight prefetch ========
    float4 xreg[16];
    {
        const float4* base = reinterpret_cast<const float4*>(x)
                           + ((size_t)(b_own * HW + s_own * 64 + rs * 16)) * C4 + c4t;
        float4 acc = make_float4(0.f, 0.f, 0.f, 0.f);
#pragma unroll
        for (int p = 0; p < 16; ++p) {
            xreg[p] = base[(size_t)p * C4];
            acc.x += xreg[p].x; acc.y += xreg[p].y;
            acc.z += xreg[p].z; acc.w += xreg[p].w;
        }
        shA4[rs * C4 + c4t] = acc;

        // weight prefetch (overlaps x loads)
        if (g >= 64) {                      // W: conv rows (g-64)*8 + k_w rows
            const float4* s1 = reinterpret_cast<const float4*>(conv_w) + (g - 64) * 1024;
            const float4* s2 = reinterpret_cast<const float4*>(k_w)    + (g - 64) * 1024;
#pragma unroll
            for (int i = 0; i < 2; ++i) wbuf4[t + i * NTHR]        = s1[t + i * NTHR];
#pragma unroll
            for (int i = 0; i < 2; ++i) wbuf4[1024 + t + i * NTHR] = s2[t + i * NTHR];
        } else if (g < 16) {                // C: q_w rows [g*32, +32)
            const float4* src = reinterpret_cast<const float4*>(q_w) + g * 4096;
#pragma unroll
            for (int i = 0; i < 8; ++i) wbuf4[t + i * NTHR] = src[t + i * NTHR];
        } else if (g < 32) {                // D: conv_w rows [(g-16)*32, +32)
            const float4* src = reinterpret_cast<const float4*>(conv_w) + (g - 16) * 4096;
#pragma unroll
            for (int i = 0; i < 8; ++i) wbuf4[t + i * NTHR] = src[t + i * NTHR];
        }
        __syncthreads();
        if (t < C4) {
            float4 a = shA4[t], p1 = shA4[C4 + t], p2 = shA4[2 * C4 + t], p3 = shA4[3 * C4 + t];
            a.x += p1.x + p2.x + p3.x;  a.y += p1.y + p2.y + p3.y;
            a.z += p1.z + p2.z + p3.z;  a.w += p1.w + p2.w + p3.w;
            g_partial4[b_own][s_own][t] = a;
        }
    }
    // colsum ticket: 16th block of each batch reduces Xsum (fixed order)
    __syncthreads();
    if (t == 0) { __threadfence(); sh_tk = atomicAdd(&c_cs[b_own].v, 1u); }
    __syncthreads();
    if (sh_tk == 15u) {
        __threadfence();                    // see other blocks' partials
        const float* gp = &g_partial4[0][0][0].x;
        float a = 0.f;
#pragma unroll
        for (int sp = 0; sp < 16; ++sp)
            a += gp[(b_own * 16 + sp) * Cc + t];
        g_xsum[b_own][t] = a;
        __syncthreads();
        if (t == 0) { __threadfence(); atomicAdd(&c_xs.v, 1u); }
    }

    // ============ W blocks (64..127): xr matvec, then Ksum matvec ============
    if (g >= 64) {
        const int a = g - 64;               // rows [a*8, a*8+8)
        WAITGE(&c_xs, 1, 8);
#pragma unroll
        for (int i = 0; i < 2; ++i)
            shA4[t + i * NTHR] = reinterpret_cast<const float4*>(g_xsum)[t + i * NTHR];
        __syncthreads();
        {   // xr = (conv_w+I) Xsum + HW*conv_b; 2 warps/row
            const int rowL = warp >> 1, h = warp & 1;
            float acc[Bb];
#pragma unroll
            for (int b = 0; b < Bb; ++b) acc[b] = 0.f;
#pragma unroll
            for (int k = 0; k < 2; ++k) {
                const int c4 = h * 64 + k * 32 + lane;
                const float4 wv = wbuf4[rowL * C4 + c4];
#pragma unroll
                for (int b = 0; b < Bb; ++b) {
                    const float4 xa = shA4[b * C4 + c4];
                    acc[b] += wv.x * xa.x + wv.y * xa.y + wv.z * xa.z + wv.w * xa.w;
                }
            }
#pragma unroll
            for (int b = 0; b < Bb; ++b)
#pragma unroll
                for (int off = 16; off; off >>= 1)
                    acc[b] += __shfl_xor_sync(0xffffffffu, acc[b], off);
            if (lane == 0)
#pragma unroll
                for (int b = 0; b < Bb; ++b) s_part[warp][b] = acc[b];
        }
        __syncthreads();
        if (t < 64) {
            const int rL = t >> 3, b = t & 7;
            const int o = a * 8 + rL;
            g_xr[b][o] = s_part[rL * 2][b] + s_part[rL * 2 + 1][b]
                       + (float)HW * conv_b[o] + shA[b][o];
        }
        ARRIVE(&c_xr[a & 3]);
        WAITGE(c_xr, 4, 64);

#pragma unroll
        for (int i = 0; i < 2; ++i)
            shA4[t + i * NTHR] = reinterpret_cast<const float4*>(g_xr)[t + i * NTHR];
        __syncthreads();
        {   // Ksum = k_w xr + HW*k_b
            const int rowL = warp >> 1, h = warp & 1;
            float acc[Bb];
#pragma unroll
            for (int b = 0; b < Bb; ++b) acc[b] = 0.f;
#pragma unroll
            for (int k = 0; k < 2; ++k) {
                const int c4 = h * 64 + k * 32 + lane;
                const float4 wv = wbuf4[1024 + rowL * C4 + c4];
#pragma unroll
                for (int b = 0; b < Bb; ++b) {
                    const float4 xa = shA4[b * C4 + c4];
                    acc[b] += wv.x * xa.x + wv.y * xa.y + wv.z * xa.z + wv.w * xa.w;
                }
            }
#pragma unroll
            for (int b = 0; b < Bb; ++b)
#pragma unroll
                for (int off = 16; off; off >>= 1)
                    acc[b] += __shfl_xor_sync(0xffffffffu, acc[b], off);
            if (lane == 0)
#pragma unroll
                for (int b = 0; b < Bb; ++b) s_part[warp][b] = acc[b];
        }
        __syncthreads();
        if (t < 64) {
            const int rL = t >> 3, b = t & 7;
            const int o = a * 8 + rL;
            g_ksum[b][o] = s_part[rL * 2][b] + s_part[rL * 2 + 1][b]
                         + (float)HW * k_b[o];
        }
        ARRIVE(&c_ks[a & 3]);
    }

    // ============ C blocks (0..15): v + wpart over own o-chunk ===============
    if (g < 16) {
        WAITGE(c_ks, 4, 64);
#pragma unroll
        for (int i = 0; i < 2; ++i)
            shA4[t + i * NTHR] = reinterpret_cast<const float4*>(g_ksum)[t + i * NTHR];
        __syncthreads();
        float tot = 0.f;
#pragma unroll
        for (int b = 0; b < Bb; ++b) tot += shA[b][t];
        shB[t] = tot;
        __syncthreads();
#pragma unroll
        for (int b = 0; b < Bb; ++b) shA[b][t] = shB[t] - shA[b][t];   // v in place
        __syncthreads();

        float vreg[Bb];
#pragma unroll
        for (int b = 0; b < Bb; ++b) vreg[b] = shA[b][g * 32 + lane];
        float acc[Bb];
#pragma unroll
        for (int b = 0; b < Bb; ++b) acc[b] = 0.f;
#pragma unroll
        for (int oo = 0; oo < 32; ++oo) {
            const float wv = wbuf[oo * Cc + t];
#pragma unroll
            for (int b = 0; b < Bb; ++b)
                acc[b] += wv * __shfl_sync(0xffffffffu, vreg[b], oo);
        }
#pragma unroll
        for (int b = 0; b < Bb; ++b) g_wpart[g][b][t] = acc[b];
        ARRIVE(&c_wp);
    }

    // ============ D blocks (16..31): inline w reduce + upart =================
    if (g >= 16 && g < 32) {
        const int j = g - 16;
        WAITGE(&c_wp, 1, 16);
        if (t < 256) {                      // w for own o-chunk, fixed order
            const int b = t >> 5, oo = t & 31;
            float s = 0.f;
#pragma unroll
            for (int jj = 0; jj < 16; ++jj) s += g_wpart[jj][b][j * 32 + oo];
            shW[b][oo] = s;
            g_w[b][j * 32 + oo] = s;        // +w residual source for dot phase
        }
        __syncthreads();

        float vreg[Bb];
#pragma unroll
        for (int b = 0; b < Bb; ++b) vreg[b] = shW[b][lane];
        float acc[Bb];
#pragma unroll
        for (int b = 0; b < Bb; ++b) acc[b] = 0.f;
#pragma unroll
        for (int oo = 0; oo < 32; ++oo) {
            const float wv = wbuf[oo * Cc + t];
#pragma unroll
            for (int b = 0; b < Bb; ++b)
                acc[b] += wv * __shfl_sync(0xffffffffu, vreg[b], oo);
        }
#pragma unroll
        for (int b = 0; b < Bb; ++b) g_upart[j][b][t] = acc[b];
        ARRIVE(&c_up);
    }

    // ============ all blocks: u assemble + dot ===============================
    WAITGE(&c_up, 1, 16);
    {
        float a = g_w[b_own][t];            // +w residual
#pragma unroll
        for (int jj = 0; jj < 16; ++jj) a += g_upart[jj][b_own][t];
        shB[t] = a;
        __syncthreads();

        const float4 uv = reinterpret_cast<const float4*>(shB)[c4t];
#pragma unroll
        for (int p = 0; p < 16; ++p) {
            const float4 xv = xreg[p];
            psum[rs * 16 + p][c4t] =
                xv.x * uv.x + xv.y * uv.y + xv.z * uv.z + xv.w * uv.w;
        }
        __syncthreads();
#pragma unroll
        for (int rr = 0; rr < 4; ++rr) {
            const int row = warp * 4 + rr;
            float sm = psum[row][lane] + psum[row][lane + 32]
                     + psum[row][lane + 64] + psum[row][lane + 96];
#pragma unroll
            for (int off = 16; off; off >>= 1)
                sm += __shfl_xor_sync(0xffffffffu, sm, off);
            if (lane == 0) sdot[row] = sm;
        }
    }
    __syncthreads();
    if (warp == 0) {
        float v0 = sdot[lane], v1 = sdot[lane + 32];
        float mn = fminf(v0, v1), mx = fmaxf(v0, v1);
#pragma unroll
        for (int off = 16; off; off >>= 1) {
            mn = fminf(mn, __shfl_xor_sync(0xffffffffu, mn, off));
            mx = fmaxf(mx, __shfl_xor_sync(0xffffffffu, mx, off));
        }
        if (lane == 0) {
            atomicMin(&g_mnk[b_own], enc(mn));
            atomicMax(&g_mxk[b_own], enc(mx));
        }
    }
    // ============ distributed epilogue: wait own batch's 16 minmax arrivals ==
    ARRIVE(&c_ep[b_own]);
    WAITGE(&c_ep[b_own], 1, 16);
    if (t < 64) {
        const float mn = dec(g_mnk[b_own]);
        const float mx = dec(g_mxk[b_own]);
        const float z = ((sdot[t] - mn) / (mx - mn) - 0.65f) / 0.15f;
        out[b_own * HW + s_own * 64 + t] = 1.0f / (1.0f + __expf(-z));
    }
    // ============ reset chain: 128th arrival resets all state (never polled) ==
    __syncthreads();
    if (t == 0) {
        unsigned old = atomicAdd(&c_fin.v, 1u);
        if (old == (unsigned)NBLK - 1u) {
#pragma unroll
            for (int i = 0; i < 8; ++i) { c_cs[i].v = 0u; c_ep[i].v = 0u; }
#pragma unroll
            for (int i = 0; i < 4; ++i) { c_xr[i].v = 0u; c_ks[i].v = 0u; }
            c_xs.v = 0u; c_wp.v = 0u; c_up.v = 0u; c_fin.v = 0u;
#pragma unroll
            for (int b = 0; b < Bb; ++b) { g_mnk[b] = 0xFFFFFFFFu; g_mxk[b] = 0u; }
            __threadfence();
        }
    }
}

// ---------------------------------------------------------------------------
extern "C" void kernel_launch(void* const* d_in, const int* in_sizes, int n_in,
                              void* d_out, int out_size) {
    const float* x      = (const float*)d_in[0];
    const float* conv_w = (const float*)d_in[1];
    const float* conv_b = (const float*)d_in[2];
    const float* q_w    = (const float*)d_in[3];
    // d_in[4] = q_b: per-batch constant, cancels in min/max normalization.
    const float* k_w    = (const float*)d_in[5];
    const float* k_b    = (const float*)d_in[6];
    float* out = (float*)d_out;

    cudaFuncSetAttribute(fused_kernel,
                         cudaFuncAttributeMaxDynamicSharedMemorySize,
                         DYN_BYTES);
    fused_kernel<<<NBLK, NTHR, DYN_BYTES>>>(x, conv_w, conv_b, q_w, k_w, k_b, out);
}